// round 1
// baseline (speedup 1.0000x reference)
#include <cuda_runtime.h>
#include <cuda_bf16.h>
#include <math.h>

// ---------------------------------------------------------------------------
// ShowAttendAndTell: 31 sequential decode steps over B=256.
//   Precompute: td = t_feat@W_td2^T ; xw = word_embs@W_td3^T + td ;
//               feat_proj = c_feats@W_feat^T
//   Per step: topdown MLP -> GRU1 -> additive attention -> language MLP
//             -> GRU2 -> classifier logits.
// All GEMMs are C = act(A[M,K] @ W[N,K]^T + bias + src + accC).
// ---------------------------------------------------------------------------

#define Bsz 256
#define Pn  256
#define Tn  32
#define NSTEP 31
#define Vn  3433
#define Hn  512
#define En  300
#define Cn  128

// ---- scratch layout (floats) ----
#define OFF_FP   0ull                                   // 256*256*512
#define SZ_FP    ((size_t)Bsz*Pn*Hn)
#define OFF_XW   (OFF_FP + SZ_FP)                       // 256*32*128
#define SZ_XW    ((size_t)Bsz*Tn*128)
#define OFF_TD   (OFF_XW + SZ_XW)
#define SZ_TD    ((size_t)Bsz*128)
#define OFF_H1   (OFF_TD + SZ_TD)
#define SZ_H1    ((size_t)Bsz*Hn)
#define OFF_H2   (OFF_H1 + SZ_H1)
#define SZ_H2    ((size_t)Bsz*Hn)
#define OFF_TMP1 (OFF_H2 + SZ_H2)
#define SZ_TMP1  ((size_t)Bsz*128)
#define OFF_S    (OFF_TMP1 + SZ_TMP1)
#define SZ_S     ((size_t)Bsz*128)
#define OFF_GX   (OFF_S + SZ_S)
#define SZ_GX    ((size_t)Bsz*1536)
#define OFF_GH   (OFF_GX + SZ_GX)
#define SZ_GH    ((size_t)Bsz*1536)
#define OFF_HW   (OFF_GH + SZ_GH)
#define SZ_HW    ((size_t)Bsz*Hn)
#define OFF_ATT  (OFF_HW + SZ_HW)
#define SZ_ATT   ((size_t)Bsz*128)
#define OFF_TL   (OFF_ATT + SZ_ATT)
#define SZ_TL    ((size_t)Bsz*128)
#define OFF_L    (OFF_TL + SZ_TL)
#define SZ_L     ((size_t)Bsz*128)
#define SCRATCH_TOTAL (OFF_L + SZ_L)

__device__ float g_scratch[SCRATCH_TOTAL];

// ---------------------------------------------------------------------------
// Generic tiled GEMM: C = act(A @ W^T + bias + src + accC)
//   A: M x K (lda), W: N x K row-major, C: M x N (ldc)
//   src: optional, src[(m/srcdiv)*ldsrc + n] added pre-activation
// ACT: 0 = none, 1 = relu, 2 = tanh
// ---------------------------------------------------------------------------
template <int ACT>
__device__ __forceinline__ float act_apply(float v) {
    if (ACT == 1) return v > 0.f ? v : 0.f;
    if (ACT == 2) return tanhf(v);
    return v;
}

template <int ACT, int BM, int BN, int BK, int TM, int TN>
__global__ void gemm_tn(const float* __restrict__ A, int lda,
                        const float* __restrict__ W,
                        const float* __restrict__ bias,
                        const float* __restrict__ src, int ldsrc, int srcdiv,
                        int accC,
                        float* __restrict__ C, int ldc,
                        int M, int N, int K) {
    const int tid = threadIdx.x;
    const int tx = tid % (BN / TN);
    const int ty = tid / (BN / TN);
    const int bm = blockIdx.y * BM;
    const int bn = blockIdx.x * BN;

    __shared__ float As[BK][BM + 1];
    __shared__ float Ws[BK][BN + 1];

    float acc[TM][TN];
#pragma unroll
    for (int i = 0; i < TM; i++)
#pragma unroll
        for (int j = 0; j < TN; j++) acc[i][j] = 0.f;

    for (int k0 = 0; k0 < K; k0 += BK) {
#pragma unroll
        for (int i = tid; i < BM * BK; i += BM * BN / (TM * TN)) {
            int k = i % BK, m = i / BK;
            int gm = bm + m, gk = k0 + k;
            As[k][m] = (gm < M && gk < K) ? A[(size_t)gm * lda + gk] : 0.f;
        }
#pragma unroll
        for (int i = tid; i < BN * BK; i += BM * BN / (TM * TN)) {
            int k = i % BK, n = i / BK;
            int gn = bn + n, gk = k0 + k;
            Ws[k][n] = (gn < N && gk < K) ? W[(size_t)gn * K + gk] : 0.f;
        }
        __syncthreads();
#pragma unroll
        for (int kk = 0; kk < BK; kk++) {
            float a[TM], b[TN];
#pragma unroll
            for (int i = 0; i < TM; i++) a[i] = As[kk][ty * TM + i];
#pragma unroll
            for (int j = 0; j < TN; j++) b[j] = Ws[kk][tx * TN + j];
#pragma unroll
            for (int i = 0; i < TM; i++)
#pragma unroll
                for (int j = 0; j < TN; j++) acc[i][j] += a[i] * b[j];
        }
        __syncthreads();
    }

#pragma unroll
    for (int i = 0; i < TM; i++) {
        int m = bm + ty * TM + i;
        if (m >= M) continue;
#pragma unroll
        for (int j = 0; j < TN; j++) {
            int n = bn + tx * TN + j;
            if (n >= N) continue;
            float v = acc[i][j];
            if (bias) v += bias[n];
            if (src) v += src[(size_t)(m / srcdiv) * ldsrc + n];
            size_t ci = (size_t)m * ldc + n;
            if (accC) v += C[ci];
            C[ci] = act_apply<ACT>(v);
        }
    }
}

template <int BM, int BN, int BK, int TM, int TN>
static void launch_gemm(int act, const float* A, int lda, const float* W,
                        const float* bias, const float* src, int ldsrc,
                        int srcdiv, int accC, float* C, int ldc,
                        int M, int N, int K) {
    dim3 grid((N + BN - 1) / BN, (M + BM - 1) / BM);
    dim3 blk((BM / TM) * (BN / TN));
    switch (act) {
        case 0: gemm_tn<0, BM, BN, BK, TM, TN><<<grid, blk>>>(A, lda, W, bias, src, ldsrc, srcdiv, accC, C, ldc, M, N, K); break;
        case 1: gemm_tn<1, BM, BN, BK, TM, TN><<<grid, blk>>>(A, lda, W, bias, src, ldsrc, srcdiv, accC, C, ldc, M, N, K); break;
        default: gemm_tn<2, BM, BN, BK, TM, TN><<<grid, blk>>>(A, lda, W, bias, src, ldsrc, srcdiv, accC, C, ldc, M, N, K); break;
    }
}

#define GEMM64(act, A, lda, W, bias, src, ldsrc, srcdiv, accC, C, ldc, M, N, K) \
    launch_gemm<64, 64, 16, 4, 4>(act, A, lda, W, bias, src, ldsrc, srcdiv, accC, C, ldc, M, N, K)
#define GEMM32(act, A, lda, W, bias, src, ldsrc, srcdiv, accC, C, ldc, M, N, K) \
    launch_gemm<32, 32, 32, 2, 2>(act, A, lda, W, bias, src, ldsrc, srcdiv, accC, C, ldc, M, N, K)

// ---------------------------------------------------------------------------
// GRU combine: h = (1-z)*n + z*h  (elementwise over B x H)
// ---------------------------------------------------------------------------
__device__ __forceinline__ float sigm(float x) { return 1.f / (1.f + expf(-x)); }

__global__ void gru_combine_kernel(const float* __restrict__ gx,
                                   const float* __restrict__ gh,
                                   float* __restrict__ h) {
    int i = blockIdx.x * blockDim.x + threadIdx.x;
    if (i >= Bsz * Hn) return;
    int b = i >> 9, o = i & 511;
    const float* gxr = gx + (size_t)b * 1536;
    const float* ghr = gh + (size_t)b * 1536;
    float r = sigm(gxr[o] + ghr[o]);
    float z = sigm(gxr[o + 512] + ghr[o + 512]);
    float n = tanhf(gxr[o + 1024] + r * ghr[o + 1024]);
    h[i] = (1.f - z) * n + z * h[i];
}

__global__ void zero_kernel(float* __restrict__ p, int n) {
    int i = blockIdx.x * blockDim.x + threadIdx.x;
    if (i < n) p[i] = 0.f;
}

// ---------------------------------------------------------------------------
// Fused attention: per batch element b (one block):
//   scores[p] = sum_h tanh(fp[b,p,h] + hW[b,h]) * Watt[h]
//   mask = softmax_p(scores); attended[b,c] = sum_p mask[p]*c_feats[b,p,c]
//   attn_out[b,p,t] = mask[p]
// ---------------------------------------------------------------------------
__global__ void attention_kernel(const float* __restrict__ fp,
                                 const float* __restrict__ cfeats,
                                 const float* __restrict__ hW,
                                 const float* __restrict__ Watt,
                                 float* __restrict__ attended,
                                 float* __restrict__ attn_out, int t) {
    int b = blockIdx.x;
    int tid = threadIdx.x;
    __shared__ float shw[Hn], swa[Hn], sc[Pn], red[256];

    for (int i = tid; i < Hn; i += 256) {
        shw[i] = hW[(size_t)b * Hn + i];
        swa[i] = Watt[i];
    }
    __syncthreads();

    int warp = tid >> 5, lane = tid & 31;
    for (int p = warp; p < Pn; p += 8) {
        const float* row = fp + ((size_t)(b * Pn + p)) * Hn;
        float acc = 0.f;
        for (int h = lane; h < Hn; h += 32) {
            float x = row[h] + shw[h];
            float th;
            asm("tanh.approx.f32 %0, %1;" : "=f"(th) : "f"(x));
            acc += th * swa[h];
        }
#pragma unroll
        for (int o = 16; o; o >>= 1) acc += __shfl_xor_sync(0xffffffffu, acc, o);
        if (!lane) sc[p] = acc;
    }
    __syncthreads();

    // softmax over 256 proposals
    float v = sc[tid];
    red[tid] = v;
    __syncthreads();
    for (int s = 128; s; s >>= 1) {
        if (tid < s) red[tid] = fmaxf(red[tid], red[tid + s]);
        __syncthreads();
    }
    float mx = red[0];
    __syncthreads();
    float e = expf(v - mx);
    red[tid] = e;
    __syncthreads();
    for (int s = 128; s; s >>= 1) {
        if (tid < s) red[tid] += red[tid + s];
        __syncthreads();
    }
    float mask = e / red[0];
    __syncthreads();
    sc[tid] = mask;
    attn_out[(size_t)b * Pn * NSTEP + (size_t)tid * NSTEP + t] = mask;
    __syncthreads();

    // attended[b, c] = sum_p mask[p] * c_feats[b,p,c]; split p range in halves
    int c = tid & 127, half = tid >> 7;
    const float* cb = cfeats + (size_t)b * Pn * Cn;
    float acc = 0.f;
    int p0 = half * 128;
    for (int p = p0; p < p0 + 128; p++) acc += sc[p] * cb[(size_t)p * Cn + c];
    red[tid] = acc;
    __syncthreads();
    if (tid < 128) attended[(size_t)b * Cn + tid] = red[tid] + red[tid + 128];
}

// ---------------------------------------------------------------------------
extern "C" void kernel_launch(void* const* d_in, const int* in_sizes, int n_in,
                              void* d_out, int out_size) {
    const float* word_embs = (const float*)d_in[0];   // (B, T, E)
    const float* t_feat    = (const float*)d_in[1];   // (B, C)
    const float* c_feats   = (const float*)d_in[2];   // (B, P, C)
    // d_in[3] = num_words (static = 32, unused)
    const float* W_td1  = (const float*)d_in[4];      // (128, H)
    const float* W_td2  = (const float*)d_in[5];      // (128, C)
    const float* W_td3  = (const float*)d_in[6];      // (128, E)
    const float* W_td   = (const float*)d_in[7];      // (128, 128)
    const float* W1_ih  = (const float*)d_in[8];      // (1536, 128)
    const float* W1_hh  = (const float*)d_in[9];      // (1536, H)
    const float* b1_ih  = (const float*)d_in[10];
    const float* b1_hh  = (const float*)d_in[11];
    const float* W_feat = (const float*)d_in[12];     // (H, C)
    const float* W_hidd = (const float*)d_in[13];     // (H, H)
    const float* W_att  = (const float*)d_in[14];     // (1, H)
    const float* W_l1   = (const float*)d_in[15];     // (128, C)
    const float* W_l2   = (const float*)d_in[16];     // (128, H)
    const float* W_l    = (const float*)d_in[17];     // (128, 128)
    const float* W2_ih  = (const float*)d_in[18];     // (1536, 128)
    const float* W2_hh  = (const float*)d_in[19];     // (1536, H)
    const float* b2_ih  = (const float*)d_in[20];
    const float* b2_hh  = (const float*)d_in[21];
    const float* W_cls  = (const float*)d_in[22];     // (V, H)
    const float* b_cls  = (const float*)d_in[23];

    float* out = (float*)d_out;
    float* out_attn = out + (size_t)Bsz * NSTEP * Vn;

    float* base = nullptr;
    cudaGetSymbolAddress((void**)&base, g_scratch);
    float* fp   = base + OFF_FP;
    float* xw   = base + OFF_XW;
    float* td   = base + OFF_TD;
    float* h1   = base + OFF_H1;
    float* h2   = base + OFF_H2;   // contiguous after h1
    float* tmp1 = base + OFF_TMP1;
    float* s    = base + OFF_S;
    float* gx   = base + OFF_GX;
    float* gh   = base + OFF_GH;
    float* hw   = base + OFF_HW;
    float* att  = base + OFF_ATT;
    float* tl   = base + OFF_TL;
    float* l    = base + OFF_L;

    // ---- init hidden states ----
    zero_kernel<<<(2 * Bsz * Hn + 255) / 256, 256>>>(h1, 2 * Bsz * Hn);

    // ---- precompute ----
    // td = t_feat @ W_td2^T                            (256 x 128, K=128)
    GEMM32(0, t_feat, Cn, W_td2, nullptr, nullptr, 0, 1, 0, td, 128, Bsz, 128, Cn);
    // xw[b,t] = word_embs[b,t] @ W_td3^T + td[b]       (8192 x 128, K=300)
    GEMM64(0, word_embs, En, W_td3, nullptr, td, 128, Tn, 0, xw, 128, Bsz * Tn, 128, En);
    // feat_proj = c_feats @ W_feat^T                   (65536 x 512, K=128)
    GEMM64(0, c_feats, Cn, W_feat, nullptr, nullptr, 0, 1, 0, fp, Hn, Bsz * Pn, Hn, Cn);

    // ---- 31 recurrent steps ----
    for (int t = 0; t < NSTEP; t++) {
        // tmp1 = tanh(h2 @ W_td1^T + xw[:,t,:])
        GEMM32(2, h2, Hn, W_td1, nullptr, xw + (size_t)t * 128, Tn * 128, 1, 0,
               tmp1, 128, Bsz, 128, Hn);
        // s = relu(tmp1 @ W_td^T)
        GEMM32(1, tmp1, 128, W_td, nullptr, nullptr, 0, 1, 0, s, 128, Bsz, 128, 128);
        // GRU1 gates
        GEMM64(0, s, 128, W1_ih, b1_ih, nullptr, 0, 1, 0, gx, 1536, Bsz, 1536, 128);
        GEMM64(0, h1, Hn, W1_hh, b1_hh, nullptr, 0, 1, 0, gh, 1536, Bsz, 1536, Hn);
        gru_combine_kernel<<<(Bsz * Hn + 255) / 256, 256>>>(gx, gh, h1);
        // hw = h1 @ W_hidd^T
        GEMM32(0, h1, Hn, W_hidd, nullptr, nullptr, 0, 1, 0, hw, Hn, Bsz, Hn, Hn);
        // attention (scores, softmax, attended, mask output)
        attention_kernel<<<Bsz, 256>>>(fp, c_feats, hw, W_att, att, out_attn, t);
        // tl = att @ W_l1^T ; tl = tanh(tl + h1 @ W_l2^T)
        GEMM32(0, att, Cn, W_l1, nullptr, nullptr, 0, 1, 0, tl, 128, Bsz, 128, Cn);
        GEMM32(2, h1, Hn, W_l2, nullptr, nullptr, 0, 1, 1, tl, 128, Bsz, 128, Hn);
        // l = relu(tl @ W_l^T)
        GEMM32(1, tl, 128, W_l, nullptr, nullptr, 0, 1, 0, l, 128, Bsz, 128, 128);
        // GRU2 gates
        GEMM64(0, l, 128, W2_ih, b2_ih, nullptr, 0, 1, 0, gx, 1536, Bsz, 1536, 128);
        GEMM64(0, h2, Hn, W2_hh, b2_hh, nullptr, 0, 1, 0, gh, 1536, Bsz, 1536, Hn);
        gru_combine_kernel<<<(Bsz * Hn + 255) / 256, 256>>>(gx, gh, h2);
        // logits = h2 @ W_cls^T + b_cls  -> lang_cap[:, t, :]
        GEMM64(0, h2, Hn, W_cls, b_cls, nullptr, 0, 1, 0,
               out + (size_t)t * Vn, NSTEP * Vn, Bsz, Vn, Hn);
    }
}

// round 3
// speedup vs baseline: 1.3307x; 1.3307x over previous
#include <cuda_runtime.h>
#include <cuda_bf16.h>
#include <math.h>

// ---------------------------------------------------------------------------
// ShowAttendAndTell — R2 restructure (resubmit after infra failure):
//   * classifier hoisted out of the 31-step loop (single big GEMM, permuted store)
//   * fused GRU kernel (gates GEMMs + combine in one launch)
//   * dual-source (concat-K) GEMM for the language-unit first layer
//   * 512-thread attention kernel with float4 loads
// ---------------------------------------------------------------------------

#define Bsz 256
#define Pn  256
#define Tn  32
#define NSTEP 31
#define Vn  3433
#define Hn  512
#define En  300
#define Cn  128

// ---- scratch layout (floats) ----
#define SZ_FP    ((size_t)Bsz*Pn*Hn)          // 33,554,432
#define SZ_XW    ((size_t)Bsz*Tn*128)         // 1,048,576
#define SZ_TD    ((size_t)Bsz*128)
#define SZ_H     ((size_t)Bsz*Hn)             // 131,072
#define SZ_HIST  ((size_t)(NSTEP+1)*Bsz*Hn)   // 4,194,304
#define SZ_SM    ((size_t)Bsz*128)

#define OFF_FP   0ull
#define OFF_XW   (OFF_FP + SZ_FP)
#define OFF_TD   (OFF_XW + SZ_XW)
#define OFF_H1A  (OFF_TD + SZ_TD)
#define OFF_H1B  (OFF_H1A + SZ_H)
#define OFF_HIST (OFF_H1B + SZ_H)
#define OFF_TMP1 (OFF_HIST + SZ_HIST)
#define OFF_S    (OFF_TMP1 + SZ_SM)
#define OFF_HW   (OFF_S + SZ_SM)
#define OFF_ATT  (OFF_HW + SZ_H)
#define OFF_TL   (OFF_ATT + SZ_SM)
#define OFF_L    (OFF_TL + SZ_SM)
#define SCRATCH_TOTAL (OFF_L + SZ_SM)

__device__ float g_scratch[SCRATCH_TOTAL];

// ---------------------------------------------------------------------------
// Generic tiled GEMM with optional concat-K dual source and src-add epilogue:
//   C = act( [A|A2] @ [W|W2]^T + bias + src )
//   A: M x K1 (lda), A2: M x (K-K1) (lda2); W: N x K1, W2: N x (K-K1)
//   src[(m/srcdiv)*ldsrc + n] added pre-activation.
// ACT: 0 = none, 1 = relu, 2 = tanh
// ---------------------------------------------------------------------------
template <int ACT>
__device__ __forceinline__ float act_apply(float v) {
    if (ACT == 1) return v > 0.f ? v : 0.f;
    if (ACT == 2) return tanhf(v);
    return v;
}

template <int ACT, int BM, int BN, int BK, int TM, int TN>
__global__ __launch_bounds__((BM / TM) * (BN / TN))
void gemm_tn(const float* __restrict__ A, int lda,
             const float* __restrict__ A2, int lda2, int K1,
             const float* __restrict__ W, const float* __restrict__ W2,
             const float* __restrict__ bias,
             const float* __restrict__ src, int ldsrc, int srcdiv,
             float* __restrict__ C, int ldc,
             int M, int N, int K) {
    const int NT = (BM / TM) * (BN / TN);
    const int tid = threadIdx.x;
    const int tx = tid % (BN / TN);
    const int ty = tid / (BN / TN);
    const int bm = blockIdx.y * BM;
    const int bn = blockIdx.x * BN;
    const int K2 = K - K1;

    __shared__ float As[BK][BM + 1];
    __shared__ float Ws[BK][BN + 1];

    float acc[TM][TN];
#pragma unroll
    for (int i = 0; i < TM; i++)
#pragma unroll
        for (int j = 0; j < TN; j++) acc[i][j] = 0.f;

    for (int k0 = 0; k0 < K; k0 += BK) {
#pragma unroll
        for (int i = tid; i < BM * BK; i += NT) {
            int k = i % BK, m = i / BK;
            int gm = bm + m, gk = k0 + k;
            float v = 0.f;
            if (gm < M && gk < K)
                v = (gk < K1) ? A[(size_t)gm * lda + gk]
                              : A2[(size_t)gm * lda2 + (gk - K1)];
            As[k][m] = v;
        }
#pragma unroll
        for (int i = tid; i < BN * BK; i += NT) {
            int k = i % BK, n = i / BK;
            int gn = bn + n, gk = k0 + k;
            float v = 0.f;
            if (gn < N && gk < K)
                v = (gk < K1) ? W[(size_t)gn * K1 + gk]
                              : W2[(size_t)gn * K2 + (gk - K1)];
            Ws[k][n] = v;
        }
        __syncthreads();
#pragma unroll
        for (int kk = 0; kk < BK; kk++) {
            float a[TM], b[TN];
#pragma unroll
            for (int i = 0; i < TM; i++) a[i] = As[kk][ty * TM + i];
#pragma unroll
            for (int j = 0; j < TN; j++) b[j] = Ws[kk][tx * TN + j];
#pragma unroll
            for (int i = 0; i < TM; i++)
#pragma unroll
                for (int j = 0; j < TN; j++) acc[i][j] += a[i] * b[j];
        }
        __syncthreads();
    }

#pragma unroll
    for (int i = 0; i < TM; i++) {
        int m = bm + ty * TM + i;
        if (m >= M) continue;
#pragma unroll
        for (int j = 0; j < TN; j++) {
            int n = bn + tx * TN + j;
            if (n >= N) continue;
            float v = acc[i][j];
            if (bias) v += bias[n];
            if (src) v += src[(size_t)(m / srcdiv) * ldsrc + n];
            C[(size_t)m * ldc + n] = act_apply<ACT>(v);
        }
    }
}

// ---------------------------------------------------------------------------
// Big-tile GEMM (128x64x16, 8x4 per thread): C = A @ W^T + bias
// PERM=1: C index = ((m & 255)*NSTEP + (m >> 8)) * ldc + n  (classifier layout)
// ---------------------------------------------------------------------------
template <int PERM>
__global__ __launch_bounds__(256)
void gemm_big(const float* __restrict__ A, int lda,
              const float* __restrict__ W,
              const float* __restrict__ bias,
              float* __restrict__ C, int ldc,
              int M, int N, int K) {
    const int BM = 128, BN = 64, BK = 16;
    const int tid = threadIdx.x;
    const int tx = tid % 16;           // 16 col-groups of 4
    const int ty = tid / 16;           // 16 row-groups of 8
    const int bm = blockIdx.y * BM;
    const int bn = blockIdx.x * BN;

    __shared__ float As[BK][BM + 4];
    __shared__ float Ws[BK][BN + 4];

    float acc[8][4];
#pragma unroll
    for (int i = 0; i < 8; i++)
#pragma unroll
        for (int j = 0; j < 4; j++) acc[i][j] = 0.f;

    for (int k0 = 0; k0 < K; k0 += BK) {
#pragma unroll
        for (int i = tid; i < BM * BK; i += 256) {
            int k = i % BK, m = i / BK;
            int gm = bm + m, gk = k0 + k;
            As[k][m] = (gm < M && gk < K) ? A[(size_t)gm * lda + gk] : 0.f;
        }
#pragma unroll
        for (int i = tid; i < BN * BK; i += 256) {
            int k = i % BK, n = i / BK;
            int gn = bn + n, gk = k0 + k;
            Ws[k][n] = (gn < N && gk < K) ? W[(size_t)gn * K + gk] : 0.f;
        }
        __syncthreads();
#pragma unroll
        for (int kk = 0; kk < BK; kk++) {
            float a[8], b[4];
#pragma unroll
            for (int i = 0; i < 8; i++) a[i] = As[kk][ty * 8 + i];
#pragma unroll
            for (int j = 0; j < 4; j++) b[j] = Ws[kk][tx * 4 + j];
#pragma unroll
            for (int i = 0; i < 8; i++)
#pragma unroll
                for (int j = 0; j < 4; j++) acc[i][j] += a[i] * b[j];
        }
        __syncthreads();
    }

#pragma unroll
    for (int i = 0; i < 8; i++) {
        int m = bm + ty * 8 + i;
        if (m >= M) continue;
#pragma unroll
        for (int j = 0; j < 4; j++) {
            int n = bn + tx * 4 + j;
            if (n >= N) continue;
            float v = acc[i][j];
            if (bias) v += bias[n];
            size_t row = PERM ? ((size_t)(m & (Bsz - 1)) * NSTEP + (m >> 8))
                              : (size_t)m;
            C[row * ldc + n] = v;
        }
    }
}

// ---------------------------------------------------------------------------
// Fused GRU: h_new = GRUCell(x[B,128], h_old[B,512])
// W_ih: (1536,128) rows [r|z|n]; W_hh: (1536,512).
// Block: 32 batch x 32 units, TM=TN=2, 256 threads. Grid (16, 8).
// ---------------------------------------------------------------------------
__global__ __launch_bounds__(256)
void gru_kernel(const float* __restrict__ x, const float* __restrict__ h_old,
                const float* __restrict__ W_ih, const float* __restrict__ W_hh,
                const float* __restrict__ b_ih, const float* __restrict__ b_hh,
                float* __restrict__ h_new) {
    const int tid = threadIdx.x;
    const int tx = tid % 16, ty = tid / 16;
    const int bn = blockIdx.x * 32;
    const int bm = blockIdx.y * 32;

    __shared__ float As[16][33], Wr[16][33], Wz[16][33], Wn[16][33];

    float ar[2][2] = {}, az[2][2] = {}, anx[2][2] = {}, anh[2][2] = {};

    for (int k0 = 0; k0 < 640; k0 += 16) {
        const bool inx = (k0 < 128);
        const float* Ap = inx ? x : h_old;
        const float* Wp = inx ? W_ih : W_hh;
        const int lda = inx ? 128 : 512;
        const int kk0 = inx ? k0 : (k0 - 128);

        for (int i = tid; i < 512; i += 256) {
            int k = i % 16, m = i / 16;
            As[k][m] = Ap[(size_t)(bm + m) * lda + kk0 + k];
        }
        for (int i = tid; i < 512; i += 256) {
            int k = i % 16, n = i / 16;
            size_t col = kk0 + k;
            Wr[k][n] = Wp[(size_t)(bn + n) * lda + col];
            Wz[k][n] = Wp[(size_t)(512 + bn + n) * lda + col];
            Wn[k][n] = Wp[(size_t)(1024 + bn + n) * lda + col];
        }
        __syncthreads();
        if (inx) {
#pragma unroll
            for (int kk = 0; kk < 16; kk++) {
                float a[2], wr[2], wz[2], wn[2];
#pragma unroll
                for (int i = 0; i < 2; i++) a[i] = As[kk][ty * 2 + i];
#pragma unroll
                for (int j = 0; j < 2; j++) {
                    wr[j] = Wr[kk][tx * 2 + j];
                    wz[j] = Wz[kk][tx * 2 + j];
                    wn[j] = Wn[kk][tx * 2 + j];
                }
#pragma unroll
                for (int i = 0; i < 2; i++)
#pragma unroll
                    for (int j = 0; j < 2; j++) {
                        ar[i][j] += a[i] * wr[j];
                        az[i][j] += a[i] * wz[j];
                        anx[i][j] += a[i] * wn[j];
                    }
            }
        } else {
#pragma unroll
            for (int kk = 0; kk < 16; kk++) {
                float a[2], wr[2], wz[2], wn[2];
#pragma unroll
                for (int i = 0; i < 2; i++) a[i] = As[kk][ty * 2 + i];
#pragma unroll
                for (int j = 0; j < 2; j++) {
                    wr[j] = Wr[kk][tx * 2 + j];
                    wz[j] = Wz[kk][tx * 2 + j];
                    wn[j] = Wn[kk][tx * 2 + j];
                }
#pragma unroll
                for (int i = 0; i < 2; i++)
#pragma unroll
                    for (int j = 0; j < 2; j++) {
                        ar[i][j] += a[i] * wr[j];
                        az[i][j] += a[i] * wz[j];
                        anh[i][j] += a[i] * wn[j];
                    }
            }
        }
        __syncthreads();
    }

#pragma unroll
    for (int i = 0; i < 2; i++) {
#pragma unroll
        for (int j = 0; j < 2; j++) {
            int m = bm + ty * 2 + i;
            int o = bn + tx * 2 + j;
            float r = 1.f / (1.f + expf(-(ar[i][j] + b_ih[o] + b_hh[o])));
            float z = 1.f / (1.f + expf(-(az[i][j] + b_ih[o + 512] + b_hh[o + 512])));
            float nn = tanhf(anx[i][j] + b_ih[o + 1024] +
                             r * (anh[i][j] + b_hh[o + 1024]));
            size_t idx = (size_t)m * Hn + o;
            float ho = h_old[idx];
            h_new[idx] = (1.f - z) * nn + z * ho;
        }
    }
}

// ---------------------------------------------------------------------------
// Fused attention, one block per batch element, 512 threads.
// ---------------------------------------------------------------------------
__global__ __launch_bounds__(512)
void attention_kernel(const float* __restrict__ fp,
                      const float* __restrict__ cfeats,
                      const float* __restrict__ hW,
                      const float* __restrict__ Watt,
                      float* __restrict__ attended,
                      float* __restrict__ attn_out, int t) {
    const int b = blockIdx.x;
    const int tid = threadIdx.x;
    __shared__ float shw[Hn], swa[Hn], sc[Pn], red[512];

    const float* hwrow = hW + (size_t)b * Hn;
    for (int i = tid; i < Hn; i += 512) {
        shw[i] = hwrow[i];
        swa[i] = Watt[i];
    }
    __syncthreads();

    const int warp = tid >> 5, lane = tid & 31;
    for (int p = warp; p < Pn; p += 16) {
        const float4* row = (const float4*)(fp + ((size_t)(b * Pn + p)) * Hn);
        float acc = 0.f;
#pragma unroll
        for (int q = 0; q < 4; q++) {
            int h4 = lane + q * 32;
            float4 v = row[h4];
            int h = h4 * 4;
            float x0 = v.x + shw[h], x1 = v.y + shw[h + 1];
            float x2 = v.z + shw[h + 2], x3 = v.w + shw[h + 3];
            float t0, t1, t2, t3;
            asm("tanh.approx.f32 %0, %1;" : "=f"(t0) : "f"(x0));
            asm("tanh.approx.f32 %0, %1;" : "=f"(t1) : "f"(x1));
            asm("tanh.approx.f32 %0, %1;" : "=f"(t2) : "f"(x2));
            asm("tanh.approx.f32 %0, %1;" : "=f"(t3) : "f"(x3));
            acc += t0 * swa[h] + t1 * swa[h + 1] + t2 * swa[h + 2] + t3 * swa[h + 3];
        }
#pragma unroll
        for (int o = 16; o; o >>= 1) acc += __shfl_xor_sync(0xffffffffu, acc, o);
        if (!lane) sc[p] = acc;
    }
    __syncthreads();

    // softmax over 256 proposals (512 threads, upper half padded)
    float v = (tid < Pn) ? sc[tid] : -1e30f;
    red[tid] = v;
    __syncthreads();
    for (int s2 = 256; s2; s2 >>= 1) {
        if (tid < s2) red[tid] = fmaxf(red[tid], red[tid + s2]);
        __syncthreads();
    }
    float mx = red[0];
    __syncthreads();
    float e = (tid < Pn) ? __expf(v - mx) : 0.f;
    red[tid] = e;
    __syncthreads();
    for (int s2 = 256; s2; s2 >>= 1) {
        if (tid < s2) red[tid] += red[tid + s2];
        __syncthreads();
    }
    float inv = 1.f / red[0];
    __syncthreads();
    if (tid < Pn) {
        float m = e * inv;
        sc[tid] = m;
        attn_out[((size_t)b * Pn + tid) * NSTEP + t] = m;
    }
    __syncthreads();

    // attended[b, c] = sum_p mask[p] * c_feats[b, p, c]
    const int c = tid & 127, seg = tid >> 7;
    const float* cb = cfeats + (size_t)b * Pn * Cn;
    float acc2 = 0.f;
    for (int p = seg * 64; p < seg * 64 + 64; p++)
        acc2 += sc[p] * cb[(size_t)p * Cn + c];
    red[tid] = acc2;
    __syncthreads();
    if (tid < Cn)
        attended[(size_t)b * Cn + tid] =
            red[tid] + red[tid + 128] + red[tid + 256] + red[tid + 384];
}

__global__ void zero_kernel(float* __restrict__ p, int n) {
    int i = blockIdx.x * blockDim.x + threadIdx.x;
    if (i < n) p[i] = 0.f;
}

// ---------------------------------------------------------------------------
extern "C" void kernel_launch(void* const* d_in, const int* in_sizes, int n_in,
                              void* d_out, int out_size) {
    const float* word_embs = (const float*)d_in[0];   // (B, T, E)
    const float* t_feat    = (const float*)d_in[1];   // (B, C)
    const float* c_feats   = (const float*)d_in[2];   // (B, P, C)
    const float* W_td1  = (const float*)d_in[4];      // (128, H)
    const float* W_td2  = (const float*)d_in[5];      // (128, C)
    const float* W_td3  = (const float*)d_in[6];      // (128, E)
    const float* W_td   = (const float*)d_in[7];      // (128, 128)
    const float* W1_ih  = (const float*)d_in[8];      // (1536, 128)
    const float* W1_hh  = (const float*)d_in[9];      // (1536, H)
    const float* b1_ih  = (const float*)d_in[10];
    const float* b1_hh  = (const float*)d_in[11];
    const float* W_feat = (const float*)d_in[12];     // (H, C)
    const float* W_hidd = (const float*)d_in[13];     // (H, H)
    const float* W_att  = (const float*)d_in[14];     // (1, H)
    const float* W_l1   = (const float*)d_in[15];     // (128, C)
    const float* W_l2   = (const float*)d_in[16];     // (128, H)
    const float* W_l    = (const float*)d_in[17];     // (128, 128)
    const float* W2_ih  = (const float*)d_in[18];     // (1536, 128)
    const float* W2_hh  = (const float*)d_in[19];     // (1536, H)
    const float* b2_ih  = (const float*)d_in[20];
    const float* b2_hh  = (const float*)d_in[21];
    const float* W_cls  = (const float*)d_in[22];     // (V, H)
    const float* b_cls  = (const float*)d_in[23];

    float* out = (float*)d_out;                       // (B, 31, V)
    float* out_attn = out + (size_t)Bsz * NSTEP * Vn; // (B, P, 31)

    float* base = nullptr;
    cudaGetSymbolAddress((void**)&base, g_scratch);
    float* fp   = base + OFF_FP;
    float* xw   = base + OFF_XW;
    float* td   = base + OFF_TD;
    float* h1a  = base + OFF_H1A;
    float* h1b  = base + OFF_H1B;
    float* hist = base + OFF_HIST;   // (NSTEP+1, B, H); slot 0 = zeros
    float* tmp1 = base + OFF_TMP1;
    float* s    = base + OFF_S;
    float* hw   = base + OFF_HW;
    float* att  = base + OFF_ATT;
    float* tl   = base + OFF_TL;
    float* l    = base + OFF_L;

    // ---- init hidden states ----
    zero_kernel<<<(int)((SZ_H + 255) / 256), 256>>>(h1a, (int)SZ_H);
    zero_kernel<<<(int)((SZ_H + 255) / 256), 256>>>(hist, (int)SZ_H);

    // ---- precompute ----
    // td = t_feat @ W_td2^T                       (256 x 128, K=128)
    gemm_tn<0, 32, 32, 32, 2, 2><<<dim3(4, 8), 256>>>(
        t_feat, Cn, nullptr, 0, Cn, W_td2, nullptr,
        nullptr, nullptr, 0, 1, td, 128, Bsz, 128, Cn);
    // xw[b,t] = word_embs[b,t] @ W_td3^T + td[b]  (8192 x 128, K=300)
    gemm_tn<0, 64, 64, 16, 4, 4><<<dim3(2, 128), 256>>>(
        word_embs, En, nullptr, 0, En, W_td3, nullptr,
        nullptr, td, 128, Tn, xw, 128, Bsz * Tn, 128, En);
    // feat_proj = c_feats @ W_feat^T              (65536 x 512, K=128)
    gemm_big<0><<<dim3(8, 512), 256>>>(
        c_feats, Cn, W_feat, nullptr, fp, Hn, Bsz * Pn, Hn, Cn);

    // ---- 31 recurrent steps ----
    for (int t = 0; t < NSTEP; t++) {
        float* h1_old = (t & 1) ? h1b : h1a;
        float* h1_new = (t & 1) ? h1a : h1b;
        float* h2_old = hist + (size_t)t * Bsz * Hn;
        float* h2_new = hist + (size_t)(t + 1) * Bsz * Hn;

        // tmp1 = tanh(h2 @ W_td1^T + xw[:,t,:])
        gemm_tn<2, 32, 32, 32, 2, 2><<<dim3(4, 8), 256>>>(
            h2_old, Hn, nullptr, 0, Hn, W_td1, nullptr,
            nullptr, xw + (size_t)t * 128, Tn * 128, 1,
            tmp1, 128, Bsz, 128, Hn);
        // s = relu(tmp1 @ W_td^T)
        gemm_tn<1, 32, 32, 32, 2, 2><<<dim3(4, 8), 256>>>(
            tmp1, 128, nullptr, 0, 128, W_td, nullptr,
            nullptr, nullptr, 0, 1, s, 128, Bsz, 128, 128);
        // h1_new = GRU1(s, h1_old)
        gru_kernel<<<dim3(16, 8), 256>>>(s, h1_old, W1_ih, W1_hh, b1_ih, b1_hh,
                                         h1_new);
        // hw = h1 @ W_hidd^T
        gemm_tn<0, 32, 32, 32, 2, 2><<<dim3(16, 8), 256>>>(
            h1_new, Hn, nullptr, 0, Hn, W_hidd, nullptr,
            nullptr, nullptr, 0, 1, hw, Hn, Bsz, Hn, Hn);
        // attention
        attention_kernel<<<Bsz, 512>>>(fp, c_feats, hw, W_att, att, out_attn, t);
        // tl = tanh(att @ W_l1^T + h1 @ W_l2^T)   (dual-source, K = 128+512)
        gemm_tn<2, 32, 32, 32, 2, 2><<<dim3(4, 8), 256>>>(
            att, Cn, h1_new, Hn, Cn, W_l1, W_l2,
            nullptr, nullptr, 0, 1, tl, 128, Bsz, 128, Cn + Hn);
        // l = relu(tl @ W_l^T)
        gemm_tn<1, 32, 32, 32, 2, 2><<<dim3(4, 8), 256>>>(
            tl, 128, nullptr, 0, 128, W_l, nullptr,
            nullptr, nullptr, 0, 1, l, 128, Bsz, 128, 128);
        // h2_new = GRU2(l, h2_old)
        gru_kernel<<<dim3(16, 8), 256>>>(l, h2_old, W2_ih, W2_hh, b2_ih, b2_hh,
                                         h2_new);
    }

    // ---- classifier over all 31 steps at once ----
    // rows m = t*256 + b of hist[1..]; store to out[(b*31 + t)*V + n]
    gemm_big<1><<<dim3((Vn + 63) / 64, (NSTEP * Bsz) / 128), 256>>>(
        hist + (size_t)Bsz * Hn, Hn, W_cls, b_cls, out, Vn,
        NSTEP * Bsz, Vn, Hn);
}

// round 5
// speedup vs baseline: 1.4547x; 1.0932x over previous
#include <cuda_runtime.h>
#include <cuda_bf16.h>
#include <math.h>

// ---------------------------------------------------------------------------
// ShowAttendAndTell — R4 resubmit (infra failure, kernel never ran):
//   * ONE persistent launch runs all 31 steps; phases separated by a manual
//     grid barrier (generation counter + atomics). Grid = multiProcessorCount
//     blocks of 256 threads, 1 block/SM guaranteed co-resident (8.4KB smem).
//   * Precompute (td, xw, feat_proj) and the big hoisted classifier GEMM stay
//     as separate conventional launches. 5 launches total.
// ---------------------------------------------------------------------------

#define Bsz 256
#define Pn  256
#define Tn  32
#define NSTEP 31
#define Vn  3433
#define Hn  512
#define En  300
#define Cn  128

// ---- scratch layout (floats) ----
#define SZ_FP    ((size_t)Bsz*Pn*Hn)
#define SZ_XW    ((size_t)Bsz*Tn*128)
#define SZ_TD    ((size_t)Bsz*128)
#define SZ_H     ((size_t)Bsz*Hn)
#define SZ_HIST  ((size_t)(NSTEP+1)*Bsz*Hn)
#define SZ_SM    ((size_t)Bsz*128)

#define OFF_FP   0ull
#define OFF_XW   (OFF_FP + SZ_FP)
#define OFF_TD   (OFF_XW + SZ_XW)
#define OFF_H1A  (OFF_TD + SZ_TD)
#define OFF_H1B  (OFF_H1A + SZ_H)
#define OFF_HIST (OFF_H1B + SZ_H)
#define OFF_TMP1 (OFF_HIST + SZ_HIST)
#define OFF_S    (OFF_TMP1 + SZ_SM)
#define OFF_HW   (OFF_S + SZ_SM)
#define OFF_ATT  (OFF_HW + SZ_H)
#define OFF_TL   (OFF_ATT + SZ_SM)
#define OFF_L    (OFF_TL + SZ_SM)
#define SCRATCH_TOTAL (OFF_L + SZ_SM)

__device__ float g_scratch[SCRATCH_TOTAL];

// ---- grid barrier state (zero-initialized at module load) ----
__device__ int g_bar_cnt;
__device__ int g_bar_gen;

__device__ __forceinline__ void grid_sync() {
    __syncthreads();
    if (threadIdx.x == 0) {
        int gen = *((volatile int*)&g_bar_gen);
        __threadfence();                       // release prior writes
        int arrived = atomicAdd(&g_bar_cnt, 1);
        if (arrived == (int)gridDim.x - 1) {
            g_bar_cnt = 0;
            __threadfence();
            atomicAdd(&g_bar_gen, 1);
        } else {
            while (*((volatile int*)&g_bar_gen) == gen) __nanosleep(40);
        }
        __threadfence();                       // acquire others' writes
    }
    __syncthreads();
}

// ---------------------------------------------------------------------------
// Phase: generic 32x32-tile GEMM over grid-strided tiles (256 threads/block).
//   C = act( [A|A2] @ [W|W2]^T + src ),  W row length = K1, W2 = K - K1.
//   For single-source pass K1 == K. ACT: 0 none, 1 relu, 2 tanh.
// smem usage: 2 * 32*33 floats from sbuf.
// ---------------------------------------------------------------------------
template <int ACT, bool DUAL, bool SRC>
__device__ void gemm_phase(float* sbuf,
                           const float* __restrict__ A, int lda,
                           const float* __restrict__ A2, int lda2,
                           const float* __restrict__ W,
                           const float* __restrict__ W2, int K1,
                           const float* __restrict__ src, int ldsrc,
                           float* __restrict__ C, int ldc,
                           int M, int N, int K) {
    float (*As)[33] = (float (*)[33])sbuf;
    float (*Ws)[33] = (float (*)[33])(sbuf + 32 * 33);
    const int tid = threadIdx.x;
    const int tx = tid & 15, ty = tid >> 4;
    const int ntn = N >> 5;
    const int ntiles = (M >> 5) * ntn;
    const int K2 = K - K1;

    for (int tile = blockIdx.x; tile < ntiles; tile += gridDim.x) {
        const int bm = (tile / ntn) << 5;
        const int bn = (tile % ntn) << 5;
        float acc[2][2] = {{0.f, 0.f}, {0.f, 0.f}};

        for (int k0 = 0; k0 < K; k0 += 32) {
#pragma unroll
            for (int i = tid; i < 1024; i += 256) {
                int k = i & 31, m = i >> 5;
                int gk = k0 + k;
                float v;
                if (!DUAL || gk < K1) v = A[(size_t)(bm + m) * lda + gk];
                else                  v = A2[(size_t)(bm + m) * lda2 + gk - K1];
                As[k][m] = v;
            }
#pragma unroll
            for (int i = tid; i < 1024; i += 256) {
                int k = i & 31, n = i >> 5;
                int gk = k0 + k;
                float v;
                if (!DUAL || gk < K1) v = W[(size_t)(bn + n) * K1 + gk];
                else                  v = W2[(size_t)(bn + n) * K2 + gk - K1];
                Ws[k][n] = v;
            }
            __syncthreads();
#pragma unroll
            for (int kk = 0; kk < 32; kk++) {
                float a0 = As[kk][ty * 2], a1 = As[kk][ty * 2 + 1];
                float b0 = Ws[kk][tx * 2], b1 = Ws[kk][tx * 2 + 1];
                acc[0][0] += a0 * b0; acc[0][1] += a0 * b1;
                acc[1][0] += a1 * b0; acc[1][1] += a1 * b1;
            }
            __syncthreads();
        }

#pragma unroll
        for (int i = 0; i < 2; i++) {
#pragma unroll
            for (int j = 0; j < 2; j++) {
                int m = bm + ty * 2 + i;
                int n = bn + tx * 2 + j;
                float v = acc[i][j];
                if (SRC) v += src[(size_t)m * ldsrc + n];
                if (ACT == 1) v = v > 0.f ? v : 0.f;
                if (ACT == 2) v = tanhf(v);
                C[(size_t)m * ldc + n] = v;
            }
        }
    }
}

// ---------------------------------------------------------------------------
// Phase: fused GRU over grid-strided 32x32 (batch x unit) tiles.
// smem: 4 * 16*33 floats from sbuf.
// ---------------------------------------------------------------------------
__device__ void gru_phase(float* sbuf,
                          const float* __restrict__ x,
                          const float* __restrict__ h_old,
                          const float* __restrict__ W_ih,
                          const float* __restrict__ W_hh,
                          const float* __restrict__ b_ih,
                          const float* __restrict__ b_hh,
                          float* __restrict__ h_new) {
    float (*As)[33] = (float (*)[33])sbuf;
    float (*Wr)[33] = (float (*)[33])(sbuf + 528);
    float (*Wz)[33] = (float (*)[33])(sbuf + 1056);
    float (*Wn)[33] = (float (*)[33])(sbuf + 1584);
    const int tid = threadIdx.x;
    const int tx = tid % 16, ty = tid / 16;

    for (int tile = blockIdx.x; tile < 128; tile += gridDim.x) {
        const int bm = (tile >> 4) << 5;   // batch tile
        const int bn = (tile & 15) << 5;   // unit tile
        float ar[2][2] = {}, az[2][2] = {}, anx[2][2] = {}, anh[2][2] = {};

        for (int k0 = 0; k0 < 640; k0 += 16) {
            const bool inx = (k0 < 128);
            const float* Ap = inx ? x : h_old;
            const float* Wp = inx ? W_ih : W_hh;
            const int lda = inx ? 128 : 512;
            const int kk0 = inx ? k0 : (k0 - 128);

            for (int i = tid; i < 512; i += 256) {
                int k = i % 16, m = i / 16;
                As[k][m] = Ap[(size_t)(bm + m) * lda + kk0 + k];
            }
            for (int i = tid; i < 512; i += 256) {
                int k = i % 16, n = i / 16;
                size_t col = kk0 + k;
                Wr[k][n] = Wp[(size_t)(bn + n) * lda + col];
                Wz[k][n] = Wp[(size_t)(512 + bn + n) * lda + col];
                Wn[k][n] = Wp[(size_t)(1024 + bn + n) * lda + col];
            }
            __syncthreads();
            if (inx) {
#pragma unroll
                for (int kk = 0; kk < 16; kk++) {
                    float a0 = As[kk][ty * 2], a1 = As[kk][ty * 2 + 1];
                    float r0 = Wr[kk][tx * 2], r1 = Wr[kk][tx * 2 + 1];
                    float z0 = Wz[kk][tx * 2], z1 = Wz[kk][tx * 2 + 1];
                    float n0 = Wn[kk][tx * 2], n1 = Wn[kk][tx * 2 + 1];
                    ar[0][0] += a0 * r0; ar[0][1] += a0 * r1; ar[1][0] += a1 * r0; ar[1][1] += a1 * r1;
                    az[0][0] += a0 * z0; az[0][1] += a0 * z1; az[1][0] += a1 * z0; az[1][1] += a1 * z1;
                    anx[0][0] += a0 * n0; anx[0][1] += a0 * n1; anx[1][0] += a1 * n0; anx[1][1] += a1 * n1;
                }
            } else {
#pragma unroll
                for (int kk = 0; kk < 16; kk++) {
                    float a0 = As[kk][ty * 2], a1 = As[kk][ty * 2 + 1];
                    float r0 = Wr[kk][tx * 2], r1 = Wr[kk][tx * 2 + 1];
                    float z0 = Wz[kk][tx * 2], z1 = Wz[kk][tx * 2 + 1];
                    float n0 = Wn[kk][tx * 2], n1 = Wn[kk][tx * 2 + 1];
                    ar[0][0] += a0 * r0; ar[0][1] += a0 * r1; ar[1][0] += a1 * r0; ar[1][1] += a1 * r1;
                    az[0][0] += a0 * z0; az[0][1] += a0 * z1; az[1][0] += a1 * z0; az[1][1] += a1 * z1;
                    anh[0][0] += a0 * n0; anh[0][1] += a0 * n1; anh[1][0] += a1 * n0; anh[1][1] += a1 * n1;
                }
            }
            __syncthreads();
        }

#pragma unroll
        for (int i = 0; i < 2; i++) {
#pragma unroll
            for (int j = 0; j < 2; j++) {
                int m = bm + ty * 2 + i;
                int o = bn + tx * 2 + j;
                float r = 1.f / (1.f + expf(-(ar[i][j] + b_ih[o] + b_hh[o])));
                float z = 1.f / (1.f + expf(-(az[i][j] + b_ih[o + 512] + b_hh[o + 512])));
                float nn = tanhf(anx[i][j] + b_ih[o + 1024] +
                                 r * (anh[i][j] + b_hh[o + 1024]));
                size_t idx = (size_t)m * Hn + o;
                h_new[idx] = (1.f - z) * nn + z * h_old[idx];
            }
        }
    }
}

// ---------------------------------------------------------------------------
// Phase: fused attention, grid-strided over batch, 256 threads.
// smem: shw[512] swa[512] sc[256] red[256] = 1536 floats from sbuf.
// ---------------------------------------------------------------------------
__device__ void attn_phase(float* sbuf,
                           const float* __restrict__ fp,
                           const float* __restrict__ cfeats,
                           const float* __restrict__ hW,
                           const float* __restrict__ Watt,
                           float* __restrict__ attended,
                           float* __restrict__ attn_out, int t) {
    float* shw = sbuf;
    float* swa = sbuf + 512;
    float* sc  = sbuf + 1024;
    float* red = sbuf + 1280;
    const int tid = threadIdx.x;
    const int warp = tid >> 5, lane = tid & 31;

    for (int b = blockIdx.x; b < Bsz; b += gridDim.x) {
        __syncthreads();    // guard smem reuse across b iterations
        const float* hwrow = hW + (size_t)b * Hn;
        for (int i = tid; i < Hn; i += 256) {
            shw[i] = hwrow[i];
            swa[i] = Watt[i];
        }
        __syncthreads();

        for (int p = warp; p < Pn; p += 8) {
            const float4* row = (const float4*)(fp + ((size_t)(b * Pn + p)) * Hn);
            float acc = 0.f;
#pragma unroll
            for (int q = 0; q < 4; q++) {
                int h4 = lane + q * 32;
                float4 v = row[h4];
                int h = h4 * 4;
                float x0 = v.x + shw[h],     x1 = v.y + shw[h + 1];
                float x2 = v.z + shw[h + 2], x3 = v.w + shw[h + 3];
                float t0, t1, t2, t3;
                asm("tanh.approx.f32 %0, %1;" : "=f"(t0) : "f"(x0));
                asm("tanh.approx.f32 %0, %1;" : "=f"(t1) : "f"(x1));
                asm("tanh.approx.f32 %0, %1;" : "=f"(t2) : "f"(x2));
                asm("tanh.approx.f32 %0, %1;" : "=f"(t3) : "f"(x3));
                acc += t0 * swa[h] + t1 * swa[h + 1] + t2 * swa[h + 2] + t3 * swa[h + 3];
            }
#pragma unroll
            for (int o = 16; o; o >>= 1) acc += __shfl_xor_sync(0xffffffffu, acc, o);
            if (!lane) sc[p] = acc;
        }
        __syncthreads();

        // softmax over 256 proposals with 256 threads
        float v = sc[tid];
        red[tid] = v;
        __syncthreads();
        for (int s2 = 128; s2; s2 >>= 1) {
            if (tid < s2) red[tid] = fmaxf(red[tid], red[tid + s2]);
            __syncthreads();
        }
        float mx = red[0];
        __syncthreads();
        float e = __expf(v - mx);
        red[tid] = e;
        __syncthreads();
        for (int s2 = 128; s2; s2 >>= 1) {
            if (tid < s2) red[tid] += red[tid + s2];
            __syncthreads();
        }
        float mask = e / red[0];
        __syncthreads();
        sc[tid] = mask;
        attn_out[((size_t)b * Pn + tid) * NSTEP + t] = mask;
        __syncthreads();

        // attended[b, c] = sum_p mask[p] * c_feats[b, p, c]
        const int c = tid & 127, seg = tid >> 7;
        const float* cb = cfeats + (size_t)b * Pn * Cn;
        float acc2 = 0.f;
        for (int p = seg * 128; p < seg * 128 + 128; p++)
            acc2 += sc[p] * cb[(size_t)p * Cn + c];
        red[tid] = acc2;
        __syncthreads();
        if (tid < Cn)
            attended[(size_t)b * Cn + tid] = red[tid] + red[tid + 128];
    }
}

// ---------------------------------------------------------------------------
// The persistent megakernel: all 31 recurrent steps.
// ---------------------------------------------------------------------------
__global__ __launch_bounds__(256)
void mega_kernel(const float* __restrict__ xw, const float* __restrict__ fp,
                 const float* __restrict__ c_feats,
                 const float* __restrict__ W_td1, const float* __restrict__ W_td,
                 const float* __restrict__ W1_ih, const float* __restrict__ W1_hh,
                 const float* __restrict__ b1_ih, const float* __restrict__ b1_hh,
                 const float* __restrict__ W_hidd, const float* __restrict__ W_att,
                 const float* __restrict__ W_l1, const float* __restrict__ W_l2,
                 const float* __restrict__ W_l,
                 const float* __restrict__ W2_ih, const float* __restrict__ W2_hh,
                 const float* __restrict__ b2_ih, const float* __restrict__ b2_hh,
                 float* h1a, float* h1b, float* hist,
                 float* tmp1, float* s, float* hw, float* att,
                 float* tl, float* l, float* out_attn) {
    __shared__ float sbuf[2112];
    const int tid = threadIdx.x;

    // phase 0: zero h1 and hist slot 0
    for (size_t i = (size_t)blockIdx.x * 256 + tid; i < SZ_H;
         i += (size_t)gridDim.x * 256) {
        h1a[i] = 0.f;
        hist[i] = 0.f;
    }
    grid_sync();

    for (int t = 0; t < NSTEP; t++) {
        const float* h1_old = (t & 1) ? h1b : h1a;
        float* h1_new = (t & 1) ? h1a : h1b;
        const float* h2_old = hist + (size_t)t * Bsz * Hn;
        float* h2_new = hist + (size_t)(t + 1) * Bsz * Hn;

        // tmp1 = tanh(h2_old @ W_td1^T + xw[:,t,:])
        gemm_phase<2, false, true>(sbuf, h2_old, Hn, nullptr, 0,
                                   W_td1, nullptr, Hn,
                                   xw + (size_t)t * 128, Tn * 128,
                                   tmp1, 128, Bsz, 128, Hn);
        grid_sync();
        // s = relu(tmp1 @ W_td^T)
        gemm_phase<1, false, false>(sbuf, tmp1, 128, nullptr, 0,
                                    W_td, nullptr, 128, nullptr, 0,
                                    s, 128, Bsz, 128, 128);
        grid_sync();
        // h1_new = GRU1(s, h1_old)
        gru_phase(sbuf, s, h1_old, W1_ih, W1_hh, b1_ih, b1_hh, h1_new);
        grid_sync();
        // hw = h1_new @ W_hidd^T
        gemm_phase<0, false, false>(sbuf, h1_new, Hn, nullptr, 0,
                                    W_hidd, nullptr, Hn, nullptr, 0,
                                    hw, Hn, Bsz, Hn, Hn);
        grid_sync();
        // attention
        attn_phase(sbuf, fp, c_feats, hw, W_att, att, out_attn, t);
        grid_sync();
        // tl = tanh(att @ W_l1^T + h1_new @ W_l2^T)   (dual, K = 128 + 512)
        gemm_phase<2, true, false>(sbuf, att, 128, h1_new, Hn,
                                   W_l1, W_l2, 128, nullptr, 0,
                                   tl, 128, Bsz, 128, 128 + Hn);
        grid_sync();
        // l = relu(tl @ W_l^T)
        gemm_phase<1, false, false>(sbuf, tl, 128, nullptr, 0,
                                    W_l, nullptr, 128, nullptr, 0,
                                    l, 128, Bsz, 128, 128);
        grid_sync();
        // h2_new = GRU2(l, h2_old)
        gru_phase(sbuf, l, h2_old, W2_ih, W2_hh, b2_ih, b2_hh, h2_new);
        grid_sync();
    }
}

// ---------------------------------------------------------------------------
// Conventional kernels for precompute + classifier (big, efficient launches).
// ---------------------------------------------------------------------------
template <int ACT, int BM, int BN, int BK, int TM, int TN>
__global__ __launch_bounds__((BM / TM) * (BN / TN))
void gemm_tn(const float* __restrict__ A, int lda,
             const float* __restrict__ W,
             const float* __restrict__ src, int ldsrc, int srcdiv,
             float* __restrict__ C, int ldc,
             int M, int N, int K) {
    const int NT = (BM / TM) * (BN / TN);
    const int tid = threadIdx.x;
    const int tx = tid % (BN / TN);
    const int ty = tid / (BN / TN);
    const int bm = blockIdx.y * BM;
    const int bn = blockIdx.x * BN;

    __shared__ float As[BK][BM + 1];
    __shared__ float Ws[BK][BN + 1];

    float acc[TM][TN];
#pragma unroll
    for (int i = 0; i < TM; i++)
#pragma unroll
        for (int j = 0; j < TN; j++) acc[i][j] = 0.f;

    for (int k0 = 0; k0 < K; k0 += BK) {
#pragma unroll
        for (int i = tid; i < BM * BK; i += NT) {
            int k = i % BK, m = i / BK;
            int gm = bm + m, gk = k0 + k;
            As[k][m] = (gm < M && gk < K) ? A[(size_t)gm * lda + gk] : 0.f;
        }
#pragma unroll
        for (int i = tid; i < BN * BK; i += NT) {
            int k = i % BK, n = i / BK;
            int gn = bn + n, gk = k0 + k;
            Ws[k][n] = (gn < N && gk < K) ? W[(size_t)gn * K + gk] : 0.f;
        }
        __syncthreads();
#pragma unroll
        for (int kk = 0; kk < BK; kk++) {
            float a[TM], b[TN];
#pragma unroll
            for (int i = 0; i < TM; i++) a[i] = As[kk][ty * TM + i];
#pragma unroll
            for (int j = 0; j < TN; j++) b[j] = Ws[kk][tx * TN + j];
#pragma unroll
            for (int i = 0; i < TM; i++)
#pragma unroll
                for (int j = 0; j < TN; j++) acc[i][j] += a[i] * b[j];
        }
        __syncthreads();
    }

#pragma unroll
    for (int i = 0; i < TM; i++) {
        int m = bm + ty * TM + i;
        if (m >= M) continue;
#pragma unroll
        for (int j = 0; j < TN; j++) {
            int n = bn + tx * TN + j;
            if (n >= N) continue;
            float v = acc[i][j];
            if (src) v += src[(size_t)(m / srcdiv) * ldsrc + n];
            if (ACT == 1) v = v > 0.f ? v : 0.f;
            if (ACT == 2) v = tanhf(v);
            C[(size_t)m * ldc + n] = v;
        }
    }
}

template <int PERM>
__global__ __launch_bounds__(256)
void gemm_big(const float* __restrict__ A, int lda,
              const float* __restrict__ W,
              const float* __restrict__ bias,
              float* __restrict__ C, int ldc,
              int M, int N, int K) {
    const int BM = 128, BN = 64, BK = 16;
    const int tid = threadIdx.x;
    const int tx = tid % 16;
    const int ty = tid / 16;
    const int bm = blockIdx.y * BM;
    const int bn = blockIdx.x * BN;

    __shared__ float As[BK][BM + 4];
    __shared__ float Ws[BK][BN + 4];

    float acc[8][4];
#pragma unroll
    for (int i = 0; i < 8; i++)
#pragma unroll
        for (int j = 0; j < 4; j++) acc[i][j] = 0.f;

    for (int k0 = 0; k0 < K; k0 += BK) {
#pragma unroll
        for (int i = tid; i < BM * BK; i += 256) {
            int k = i % BK, m = i / BK;
            int gm = bm + m, gk = k0 + k;
            As[k][m] = (gm < M && gk < K) ? A[(size_t)gm * lda + gk] : 0.f;
        }
#pragma unroll
        for (int i = tid; i < BN * BK; i += 256) {
            int k = i % BK, n = i / BK;
            int gn = bn + n, gk = k0 + k;
            Ws[k][n] = (gn < N && gk < K) ? W[(size_t)gn * K + gk] : 0.f;
        }
        __syncthreads();
#pragma unroll
        for (int kk = 0; kk < BK; kk++) {
            float a[8], b[4];
#pragma unroll
            for (int i = 0; i < 8; i++) a[i] = As[kk][ty * 8 + i];
#pragma unroll
            for (int j = 0; j < 4; j++) b[j] = Ws[kk][tx * 4 + j];
#pragma unroll
            for (int i = 0; i < 8; i++)
#pragma unroll
                for (int j = 0; j < 4; j++) acc[i][j] += a[i] * b[j];
        }
        __syncthreads();
    }

#pragma unroll
    for (int i = 0; i < 8; i++) {
        int m = bm + ty * 8 + i;
        if (m >= M) continue;
#pragma unroll
        for (int j = 0; j < 4; j++) {
            int n = bn + tx * 4 + j;
            if (n >= N) continue;
            float v = acc[i][j];
            if (bias) v += bias[n];
            size_t row = PERM ? ((size_t)(m & (Bsz - 1)) * NSTEP + (m >> 8))
                              : (size_t)m;
            C[row * ldc + n] = v;
        }
    }
}

// ---------------------------------------------------------------------------
extern "C" void kernel_launch(void* const* d_in, const int* in_sizes, int n_in,
                              void* d_out, int out_size) {
    const float* word_embs = (const float*)d_in[0];
    const float* t_feat    = (const float*)d_in[1];
    const float* c_feats   = (const float*)d_in[2];
    const float* W_td1  = (const float*)d_in[4];
    const float* W_td2  = (const float*)d_in[5];
    const float* W_td3  = (const float*)d_in[6];
    const float* W_td   = (const float*)d_in[7];
    const float* W1_ih  = (const float*)d_in[8];
    const float* W1_hh  = (const float*)d_in[9];
    const float* b1_ih  = (const float*)d_in[10];
    const float* b1_hh  = (const float*)d_in[11];
    const float* W_feat = (const float*)d_in[12];
    const float* W_hidd = (const float*)d_in[13];
    const float* W_att  = (const float*)d_in[14];
    const float* W_l1   = (const float*)d_in[15];
    const float* W_l2   = (const float*)d_in[16];
    const float* W_l    = (const float*)d_in[17];
    const float* W2_ih  = (const float*)d_in[18];
    const float* W2_hh  = (const float*)d_in[19];
    const float* b2_ih  = (const float*)d_in[20];
    const float* b2_hh  = (const float*)d_in[21];
    const float* W_cls  = (const float*)d_in[22];
    const float* b_cls  = (const float*)d_in[23];

    float* out = (float*)d_out;                       // (B, 31, V)
    float* out_attn = out + (size_t)Bsz * NSTEP * Vn; // (B, P, 31)

    float* base = nullptr;
    cudaGetSymbolAddress((void**)&base, g_scratch);
    float* fp   = base + OFF_FP;
    float* xw   = base + OFF_XW;
    float* td   = base + OFF_TD;
    float* h1a  = base + OFF_H1A;
    float* h1b  = base + OFF_H1B;
    float* hist = base + OFF_HIST;
    float* tmp1 = base + OFF_TMP1;
    float* s    = base + OFF_S;
    float* hw   = base + OFF_HW;
    float* att  = base + OFF_ATT;
    float* tl   = base + OFF_TL;
    float* l    = base + OFF_L;

    // grid size for the persistent megakernel: one block per SM
    int G = 148, dev = 0;
    cudaGetDevice(&dev);
    if (cudaDeviceGetAttribute(&G, cudaDevAttrMultiProcessorCount, dev) !=
        cudaSuccess || G <= 0)
        G = 64;   // conservative fallback, still co-resident

    // ---- precompute ----
    // td = t_feat @ W_td2^T
    gemm_tn<0, 32, 32, 32, 2, 2><<<dim3(4, 8), 256>>>(
        t_feat, Cn, W_td2, nullptr, 0, 1, td, 128, Bsz, 128, Cn);
    // xw[b,t] = word_embs[b,t] @ W_td3^T + td[b]
    gemm_tn<0, 64, 64, 16, 4, 4><<<dim3(2, 128), 256>>>(
        word_embs, En, W_td3, td, 128, Tn, xw, 128, Bsz * Tn, 128, En);
    // feat_proj = c_feats @ W_feat^T
    gemm_big<0><<<dim3(8, 512), 256>>>(
        c_feats, Cn, W_feat, nullptr, fp, Hn, Bsz * Pn, Hn, Cn);

    // ---- the 31-step persistent megakernel ----
    mega_kernel<<<G, 256>>>(xw, fp, c_feats,
                            W_td1, W_td, W1_ih, W1_hh, b1_ih, b1_hh,
                            W_hidd, W_att, W_l1, W_l2, W_l,
                            W2_ih, W2_hh, b2_ih, b2_hh,
                            h1a, h1b, hist, tmp1, s, hw, att, tl, l,
                            out_attn);

    // ---- classifier over all 31 steps at once ----
    gemm_big<1><<<dim3((Vn + 63) / 64, (NSTEP * Bsz) / 128), 256>>>(
        hist + (size_t)Bsz * Hn, Hn, W_cls, b_cls, out, Vn,
        NSTEP * Bsz, Vn, Hn);
}